// round 14
// baseline (speedup 1.0000x reference)
#include <cuda_runtime.h>
#include <cuda_fp16.h>
#include <math.h>

#define NUM_B 2
#define NUM_C 256
#define NUM_H 256
#define NUM_W 256
#define NUM_N 512
#define OUT_H 7
#define OUT_W 7
#define NBIN 49
#define HW (NUM_H * NUM_W)
#define CHW (NUM_C * HW)
#define C_HALF 128
#define SOUT_PAD 133
#define TS 8   // h-slices per transpose block

// fp16 NHWC copy of x: xT[b][y][x][c]  (64 MB total)
__device__ __half xT_buf[(size_t)NUM_B * NUM_H * NUM_W * NUM_C];

// ---------------------------------------------------------------------------
// Kernel A: NCHW fp32 -> NHWC fp16 transpose, 8 h-slices per block.
// grid (W/32, C/32, B*H/8), block (8, 32). Thread: 8 independent LDG.128.
// ---------------------------------------------------------------------------
__global__ __launch_bounds__(256) void transpose_kernel(const float* __restrict__ x)
{
    __shared__ float tile[TS][32][33];

    const int w0 = blockIdx.x * 32;
    const int c0 = blockIdx.y * 32;
    const int z  = blockIdx.z;           // b*32 + h/8
    const int b  = z >> 5;
    const int h0 = (z & 31) * TS;
    const int tx = threadIdx.x;          // 0..7
    const int ty = threadIdx.y;          // 0..31

    // 8 independent coalesced streaming LDG.128 (different h-slices).
    const float* src = x + (((size_t)b * NUM_C + c0 + ty) * NUM_H + h0) * NUM_W
                         + w0 + tx * 4;
    float4 v[TS];
    #pragma unroll
    for (int k = 0; k < TS; ++k)
        v[k] = __ldcs(reinterpret_cast<const float4*>(src + (size_t)k * NUM_W));

    #pragma unroll
    for (int k = 0; k < TS; ++k) {
        tile[k][ty][tx * 4 + 0] = v[k].x;
        tile[k][ty][tx * 4 + 1] = v[k].y;
        tile[k][ty][tx * 4 + 2] = v[k].z;
        tile[k][ty][tx * 4 + 3] = v[k].w;
    }
    __syncthreads();

    // 8 independent 8B stores: w = w0+ty, 4 consecutive channels as fp16.
    #pragma unroll
    for (int k = 0; k < TS; ++k) {
        __half2 lo = __floats2half2_rn(tile[k][tx * 4 + 0][ty], tile[k][tx * 4 + 1][ty]);
        __half2 hi = __floats2half2_rn(tile[k][tx * 4 + 2][ty], tile[k][tx * 4 + 3][ty]);
        uint2 pak;
        pak.x = *reinterpret_cast<unsigned int*>(&lo);
        pak.y = *reinterpret_cast<unsigned int*>(&hi);

        __half* dst = xT_buf + (((size_t)b * NUM_H + h0 + k) * NUM_W + w0 + ty) * NUM_C
                             + c0 + tx * 4;
        *reinterpret_cast<uint2*>(dst) = pak;
    }
}

// ---------------------------------------------------------------------------
// Kernel B: RROI pool from fp16 NHWC. grid = 2048 (roi * 2 halves), block 256.
// Bin loop unrolled by 2: 8 corner loads batched before compute (MLP 8).
// ---------------------------------------------------------------------------
__global__ __launch_bounds__(256) void rroi_pool_kernel(
    const float* __restrict__ boxes,
    float* __restrict__ out)
{
    __shared__ int   s_pos[NBIN][4];        // clamped corner spatial idx y*256+x
    __shared__ float s_wgt[NBIN][4];        // validity-folded weights lt,rt,rb,lb
    __shared__ float s_out[NBIN][SOUT_PAD]; // [bin][channel-within-half]

    const int roi  = blockIdx.x >> 1;
    const int half = blockIdx.x & 1;
    const int tid  = threadIdx.x;

    if (tid < NBIN) {
        const float* bx = boxes + roi * 5;
        float cx  = __fmul_rn(bx[0], 0.25f);
        float cy  = __fmul_rn(bx[1], 0.25f);
        float w   = __fmul_rn(bx[2], 0.25f);
        float h   = __fmul_rn(bx[3], 0.25f);
        float ang = __fmul_rn(bx[4], 0.017453292519943295f);

        float Sx = __fdiv_rn(w, 7.0f);
        float Sy = __fdiv_rn(h, 7.0f);
        float ca = cosf(ang);
        float sa = sinf(ang);

        const float dxc = -3.5f;
        const float dyc = -3.5f;

        float M00 = __fmul_rn(ca, Sx);
        float M01 = __fmul_rn(sa, Sy);
        float M02 = __fadd_rn(__fadd_rn(__fmul_rn(__fmul_rn(ca, Sx), dxc),
                                        __fmul_rn(__fmul_rn(sa, Sy), dyc)), cx);
        float M10 = __fmul_rn(-sa, Sx);
        float M11 = __fmul_rn(ca, Sy);
        float M12 = __fadd_rn(__fadd_rn(__fmul_rn(__fmul_rn(-sa, Sx), dxc),
                                        __fmul_rn(__fmul_rn(ca, Sy), dyc)), cy);

        int ph = tid / OUT_W;
        int pw = tid - ph * OUT_W;

        const float offx[4] = {0.f, 0.f, 1.f, 1.f};
        const float offy[4] = {0.f, 1.f, 0.f, 1.f};

        float minX =  3.0e38f, maxX = -3.0e38f;
        float minY =  3.0e38f, maxY = -3.0e38f;
        #pragma unroll
        for (int k = 0; k < 4; ++k) {
            float pwc = (float)pw + offx[k];
            float phc = (float)ph + offy[k];
            float X = __fadd_rn(__fadd_rn(__fmul_rn(M00, pwc), __fmul_rn(M01, phc)), M02);
            float Y = __fadd_rn(__fadd_rn(__fmul_rn(M10, pwc), __fmul_rn(M11, phc)), M12);
            minX = fminf(minX, X); maxX = fmaxf(maxX, X);
            minY = fminf(minY, Y); maxY = fmaxf(maxY, Y);
        }

        float lM = fmaxf(rintf(minX), 0.0f);
        float rM = fminf(rintf(maxX), (float)(NUM_W - 1));
        float tM = fmaxf(rintf(minY), 0.0f);
        float bM = fminf(rintf(maxY), (float)(NUM_H - 1));

        float bcx = __fmul_rn(__fadd_rn(lM, rM), 0.5f);
        float bcy = __fmul_rn(__fadd_rn(tM, bM), 0.5f);

        float flx = floorf(bcx);
        float fly = floorf(bcy);
        int il = (int)flx;
        int it = (int)fly;
        int ir = (int)ceilf(bcx);
        int ib = (int)ceilf(bcy);
        float rx = __fsub_rn(bcx, flx);
        float ry = __fsub_rn(bcy, fly);

        float omrx = __fsub_rn(1.0f, rx);
        float omry = __fsub_rn(1.0f, ry);
        float wlt = __fmul_rn(omrx, omry);
        float wrt = __fmul_rn(rx,   omry);
        float wrb = __fmul_rn(rx,   ry);
        float wlb = __fmul_rn(omrx, ry);

        bool vl = (il >= 0) && (il < NUM_W);
        bool vr = (ir >= 0) && (ir < NUM_W);
        bool vt = (it >= 0) && (it < NUM_H);
        bool vb = (ib >= 0) && (ib < NUM_H);

        int cl = min(max(il, 0), NUM_W - 1);
        int cr = min(max(ir, 0), NUM_W - 1);
        int ct = min(max(it, 0), NUM_H - 1);
        int cb = min(max(ib, 0), NUM_H - 1);

        s_pos[tid][0] = ct * NUM_W + cl;
        s_pos[tid][1] = ct * NUM_W + cr;
        s_pos[tid][2] = cb * NUM_W + cr;
        s_pos[tid][3] = cb * NUM_W + cl;

        s_wgt[tid][0] = (vt && vl) ? wlt : 0.0f;
        s_wgt[tid][1] = (vt && vr) ? wrt : 0.0f;
        s_wgt[tid][2] = (vb && vr) ? wrb : 0.0f;
        s_wgt[tid][3] = (vb && vl) ? wlb : 0.0f;
    }
    __syncthreads();

    const int wid  = tid >> 5;
    const int lane = tid & 31;

    // base: xT[b][.][.][half*128 + lane*4]  (fp16)
    const __half* base = xT_buf + ((size_t)(roi >> 9) * HW * NUM_C)
                       + half * C_HALF + lane * 4;

    for (int bin = wid; bin < NBIN; bin += 16) {
        const int  bin2 = bin + 8;
        const bool has2 = (bin2 < NBIN);

        float wA[4], wB[4];
        #pragma unroll
        for (int k = 0; k < 4; ++k) {
            wA[k] = s_wgt[bin][k];
            wB[k] = has2 ? s_wgt[bin2][k] : 0.0f;
        }

        // Batched load phase: up to 8 independent predicated LDG.64.
        uint2 pA[4], pB[4];
        #pragma unroll
        for (int k = 0; k < 4; ++k) {
            pA[k] = make_uint2(0u, 0u);
            pB[k] = make_uint2(0u, 0u);
        }
        #pragma unroll
        for (int k = 0; k < 4; ++k)
            if (wA[k] != 0.0f)
                pA[k] = *reinterpret_cast<const uint2*>(base + (size_t)s_pos[bin][k] * NUM_C);
        #pragma unroll
        for (int k = 0; k < 4; ++k)
            if (wB[k] != 0.0f)
                pB[k] = *reinterpret_cast<const uint2*>(base + (size_t)s_pos[bin2][k] * NUM_C);

        // Compute bin
        {
            float4 acc = make_float4(0.f, 0.f, 0.f, 0.f);
            #pragma unroll
            for (int k = 0; k < 4; ++k) {
                __half2 h0 = *reinterpret_cast<__half2*>(&pA[k].x);
                __half2 h1 = *reinterpret_cast<__half2*>(&pA[k].y);
                float2 f0 = __half22float2(h0);
                float2 f1 = __half22float2(h1);
                acc.x += f0.x * wA[k];
                acc.y += f0.y * wA[k];
                acc.z += f1.x * wA[k];
                acc.w += f1.y * wA[k];
            }
            s_out[bin][lane * 4 + 0] = fmaxf(acc.x, 0.0f);
            s_out[bin][lane * 4 + 1] = fmaxf(acc.y, 0.0f);
            s_out[bin][lane * 4 + 2] = fmaxf(acc.z, 0.0f);
            s_out[bin][lane * 4 + 3] = fmaxf(acc.w, 0.0f);
        }
        // Compute bin2
        if (has2) {
            float4 acc = make_float4(0.f, 0.f, 0.f, 0.f);
            #pragma unroll
            for (int k = 0; k < 4; ++k) {
                __half2 h0 = *reinterpret_cast<__half2*>(&pB[k].x);
                __half2 h1 = *reinterpret_cast<__half2*>(&pB[k].y);
                float2 f0 = __half22float2(h0);
                float2 f1 = __half22float2(h1);
                acc.x += f0.x * wB[k];
                acc.y += f0.y * wB[k];
                acc.z += f1.x * wB[k];
                acc.w += f1.y * wB[k];
            }
            s_out[bin2][lane * 4 + 0] = fmaxf(acc.x, 0.0f);
            s_out[bin2][lane * 4 + 1] = fmaxf(acc.y, 0.0f);
            s_out[bin2][lane * 4 + 2] = fmaxf(acc.z, 0.0f);
            s_out[bin2][lane * 4 + 3] = fmaxf(acc.w, 0.0f);
        }
    }
    __syncthreads();

    // Coalesced write-out: 128 channels x 49 bins = 6272 floats per block.
    float* ob = out + (size_t)roi * (NUM_C * NBIN) + (size_t)half * C_HALF * NBIN;
    for (int i = tid; i < C_HALF * NBIN; i += 256) {
        int c   = i / NBIN;
        int bin = i - c * NBIN;
        ob[i] = s_out[bin][c];
    }
}

extern "C" void kernel_launch(void* const* d_in, const int* in_sizes, int n_in,
                              void* d_out, int out_size) {
    const float* x     = (const float*)d_in[0];   // (2,256,256,256) f32
    const float* boxes = (const float*)d_in[1];   // (2,512,5) f32
    float* out = (float*)d_out;                   // (1024,256,7,7) f32
    (void)in_sizes; (void)n_in; (void)out_size;

    dim3 tgrid(NUM_W / 32, NUM_C / 32, NUM_B * NUM_H / TS);
    dim3 tblk(8, 32);
    transpose_kernel<<<tgrid, tblk>>>(x);

    rroi_pool_kernel<<<NUM_B * NUM_N * 2, 256>>>(boxes, out);
}

// round 16
// speedup vs baseline: 1.1975x; 1.1975x over previous
#include <cuda_runtime.h>
#include <cuda_fp16.h>
#include <math.h>

#define NUM_B 2
#define NUM_C 256
#define NUM_H 256
#define NUM_W 256
#define NUM_N 512
#define OUT_H 7
#define OUT_W 7
#define NBIN 49
#define HW (NUM_H * NUM_W)
#define CHW (NUM_C * HW)
#define C_HALF 128
#define SOUT_PAD 133

// fp16 NHWC copy of x: xT[b][y][x][c]  (64 MB total)
__device__ __half xT_buf[(size_t)NUM_B * NUM_H * NUM_W * NUM_C];

// ---------------------------------------------------------------------------
// Kernel A: NCHW fp32 -> NHWC fp16 transpose, 4 h-slices per block (R13).
// grid (W/32, C/32, B*H/4), block (8, 32).
// ---------------------------------------------------------------------------
__global__ __launch_bounds__(256) void transpose_kernel(const float* __restrict__ x)
{
    __shared__ float tile[4][32][33];

    const int w0 = blockIdx.x * 32;
    const int c0 = blockIdx.y * 32;
    const int z  = blockIdx.z;           // b*64 + h/4
    const int b  = z >> 6;
    const int h0 = (z & 63) * 4;
    const int tx = threadIdx.x;          // 0..7
    const int ty = threadIdx.y;          // 0..31

    const float* src = x + (((size_t)b * NUM_C + c0 + ty) * NUM_H + h0) * NUM_W
                         + w0 + tx * 4;
    float4 v[4];
    #pragma unroll
    for (int k = 0; k < 4; ++k)
        v[k] = *reinterpret_cast<const float4*>(src + (size_t)k * NUM_W);

    #pragma unroll
    for (int k = 0; k < 4; ++k) {
        tile[k][ty][tx * 4 + 0] = v[k].x;
        tile[k][ty][tx * 4 + 1] = v[k].y;
        tile[k][ty][tx * 4 + 2] = v[k].z;
        tile[k][ty][tx * 4 + 3] = v[k].w;
    }
    __syncthreads();

    #pragma unroll
    for (int k = 0; k < 4; ++k) {
        __half2 lo = __floats2half2_rn(tile[k][tx * 4 + 0][ty], tile[k][tx * 4 + 1][ty]);
        __half2 hi = __floats2half2_rn(tile[k][tx * 4 + 2][ty], tile[k][tx * 4 + 3][ty]);
        uint2 pak;
        pak.x = *reinterpret_cast<unsigned int*>(&lo);
        pak.y = *reinterpret_cast<unsigned int*>(&hi);

        __half* dst = xT_buf + (((size_t)b * NUM_H + h0 + k) * NUM_W + w0 + ty) * NUM_C
                             + c0 + tx * 4;
        *reinterpret_cast<uint2*>(dst) = pak;
    }
}

// ---------------------------------------------------------------------------
// Kernel B: RROI pool from fp16 NHWC. grid = 2048 (roi * 2 halves), block 256.
// Half-warp per bin, uint4 (8-channel) gathers.
// ---------------------------------------------------------------------------
__global__ __launch_bounds__(256) void rroi_pool_kernel(
    const float* __restrict__ boxes,
    float* __restrict__ out)
{
    __shared__ int   s_pos[NBIN][4];
    __shared__ float s_wgt[NBIN][4];
    __shared__ float s_out[NBIN][SOUT_PAD];

    const int roi  = blockIdx.x >> 1;
    const int half = blockIdx.x & 1;
    const int tid  = threadIdx.x;

    if (tid < NBIN) {
        const float* bx = boxes + roi * 5;
        float cx  = __fmul_rn(bx[0], 0.25f);
        float cy  = __fmul_rn(bx[1], 0.25f);
        float w   = __fmul_rn(bx[2], 0.25f);
        float h   = __fmul_rn(bx[3], 0.25f);
        float ang = __fmul_rn(bx[4], 0.017453292519943295f);

        float Sx = __fdiv_rn(w, 7.0f);
        float Sy = __fdiv_rn(h, 7.0f);
        float ca = cosf(ang);
        float sa = sinf(ang);

        const float dxc = -3.5f;
        const float dyc = -3.5f;

        float M00 = __fmul_rn(ca, Sx);
        float M01 = __fmul_rn(sa, Sy);
        float M02 = __fadd_rn(__fadd_rn(__fmul_rn(__fmul_rn(ca, Sx), dxc),
                                        __fmul_rn(__fmul_rn(sa, Sy), dyc)), cx);
        float M10 = __fmul_rn(-sa, Sx);
        float M11 = __fmul_rn(ca, Sy);
        float M12 = __fadd_rn(__fadd_rn(__fmul_rn(__fmul_rn(-sa, Sx), dxc),
                                        __fmul_rn(__fmul_rn(ca, Sy), dyc)), cy);

        int ph = tid / OUT_W;
        int pw = tid - ph * OUT_W;

        const float offx[4] = {0.f, 0.f, 1.f, 1.f};
        const float offy[4] = {0.f, 1.f, 0.f, 1.f};

        float minX =  3.0e38f, maxX = -3.0e38f;
        float minY =  3.0e38f, maxY = -3.0e38f;
        #pragma unroll
        for (int k = 0; k < 4; ++k) {
            float pwc = (float)pw + offx[k];
            float phc = (float)ph + offy[k];
            float X = __fadd_rn(__fadd_rn(__fmul_rn(M00, pwc), __fmul_rn(M01, phc)), M02);
            float Y = __fadd_rn(__fadd_rn(__fmul_rn(M10, pwc), __fmul_rn(M11, phc)), M12);
            minX = fminf(minX, X); maxX = fmaxf(maxX, X);
            minY = fminf(minY, Y); maxY = fmaxf(maxY, Y);
        }

        float lM = fmaxf(rintf(minX), 0.0f);
        float rM = fminf(rintf(maxX), (float)(NUM_W - 1));
        float tM = fmaxf(rintf(minY), 0.0f);
        float bM = fminf(rintf(maxY), (float)(NUM_H - 1));

        float bcx = __fmul_rn(__fadd_rn(lM, rM), 0.5f);
        float bcy = __fmul_rn(__fadd_rn(tM, bM), 0.5f);

        float flx = floorf(bcx);
        float fly = floorf(bcy);
        int il = (int)flx;
        int it = (int)fly;
        int ir = (int)ceilf(bcx);
        int ib = (int)ceilf(bcy);
        float rx = __fsub_rn(bcx, flx);
        float ry = __fsub_rn(bcy, fly);

        float omrx = __fsub_rn(1.0f, rx);
        float omry = __fsub_rn(1.0f, ry);
        float wlt = __fmul_rn(omrx, omry);
        float wrt = __fmul_rn(rx,   omry);
        float wrb = __fmul_rn(rx,   ry);
        float wlb = __fmul_rn(omrx, ry);

        bool vl = (il >= 0) && (il < NUM_W);
        bool vr = (ir >= 0) && (ir < NUM_W);
        bool vt = (it >= 0) && (it < NUM_H);
        bool vb = (ib >= 0) && (ib < NUM_H);

        int cl = min(max(il, 0), NUM_W - 1);
        int cr = min(max(ir, 0), NUM_W - 1);
        int ct = min(max(it, 0), NUM_H - 1);
        int cb = min(max(ib, 0), NUM_H - 1);

        s_pos[tid][0] = ct * NUM_W + cl;
        s_pos[tid][1] = ct * NUM_W + cr;
        s_pos[tid][2] = cb * NUM_W + cr;
        s_pos[tid][3] = cb * NUM_W + cl;

        s_wgt[tid][0] = (vt && vl) ? wlt : 0.0f;
        s_wgt[tid][1] = (vt && vr) ? wrt : 0.0f;
        s_wgt[tid][2] = (vb && vr) ? wrb : 0.0f;
        s_wgt[tid][3] = (vb && vl) ? wlb : 0.0f;
    }
    __syncthreads();

    const int wid  = tid >> 5;       // 0..7
    const int lane = tid & 31;
    const int hw   = lane >> 4;      // half-warp: 0 or 1
    const int l16  = lane & 15;      // lane within half-warp

    // base: xT[b][.][.][half*128 + l16*8]  (fp16, 16B-aligned)
    const __half* base = xT_buf + ((size_t)(roi >> 9) * HW * NUM_C)
                       + half * C_HALF + l16 * 8;

    // Each warp: 2 bins per iteration (one per half-warp). 8 warps -> 16 bins/iter.
    // bb0 sweeps {wid*2, +16, +32, +48} -> bins 0..63 covered; valid<49 masks.
    for (int bb0 = wid * 2; bb0 < 64; bb0 += 16) {
        const int  bin   = bb0 + hw;
        const bool valid = (bin < NBIN);
        const int  binc  = valid ? bin : NBIN - 1;

        float acc[8];
        #pragma unroll
        for (int j = 0; j < 8; ++j) acc[j] = 0.0f;

        #pragma unroll
        for (int k = 0; k < 4; ++k) {
            float wgt = valid ? s_wgt[binc][k] : 0.0f;   // half-warp-uniform
            if (wgt != 0.0f) {
                uint4 pak = *reinterpret_cast<const uint4*>(
                    base + (size_t)s_pos[binc][k] * NUM_C);
                float2 f0 = __half22float2(*reinterpret_cast<__half2*>(&pak.x));
                float2 f1 = __half22float2(*reinterpret_cast<__half2*>(&pak.y));
                float2 f2 = __half22float2(*reinterpret_cast<__half2*>(&pak.z));
                float2 f3 = __half22float2(*reinterpret_cast<__half2*>(&pak.w));
                acc[0] += f0.x * wgt;
                acc[1] += f0.y * wgt;
                acc[2] += f1.x * wgt;
                acc[3] += f1.y * wgt;
                acc[4] += f2.x * wgt;
                acc[5] += f2.y * wgt;
                acc[6] += f3.x * wgt;
                acc[7] += f3.y * wgt;
            }
        }
        if (valid) {
            #pragma unroll
            for (int j = 0; j < 8; ++j)
                s_out[bin][l16 * 8 + j] = fmaxf(acc[j], 0.0f);
        }
    }
    __syncthreads();

    // Coalesced write-out: 128 channels x 49 bins, incremental (c,bin) tracking.
    float* ob = out + (size_t)roi * (NUM_C * NBIN) + (size_t)half * C_HALF * NBIN;
    {
        int c   = tid / NBIN;
        int bin = tid - c * NBIN;
        #pragma unroll 4
        for (int i = tid; i < C_HALF * NBIN; i += 256) {
            ob[i] = s_out[bin][c];
            bin += 11;                 // 256 = 5*49 + 11
            c   += 5;
            if (bin >= NBIN) { bin -= NBIN; c += 1; }
        }
    }
}

extern "C" void kernel_launch(void* const* d_in, const int* in_sizes, int n_in,
                              void* d_out, int out_size) {
    const float* x     = (const float*)d_in[0];   // (2,256,256,256) f32
    const float* boxes = (const float*)d_in[1];   // (2,512,5) f32
    float* out = (float*)d_out;                   // (1024,256,7,7) f32
    (void)in_sizes; (void)n_in; (void)out_size;

    dim3 tgrid(NUM_W / 32, NUM_C / 32, NUM_B * NUM_H / 4);
    dim3 tblk(8, 32);
    transpose_kernel<<<tgrid, tblk>>>(x);

    rroi_pool_kernel<<<NUM_B * NUM_N * 2, 256>>>(boxes, out);
}